// round 9
// baseline (speedup 1.0000x reference)
#include <cuda_runtime.h>
#include <math.h>
#include <float.h>

// layers: C = {64,128,256,512}, HW = {3136,784,196,49}, B=256, R=2000
#define NB 256
#define NR 2000
#define NRP 2048

__constant__ int c_C[4]    = {64, 128, 256, 512};
__constant__ int c_HW[4]   = {3136, 784, 196, 49};
__constant__ int c_qoff[4] = {0, 16384, 49152, 114688};

// scratch (static device globals; no allocation)
__device__ __align__(16) float g_fq[245760];        // pooled queries
__device__ __align__(16) float g_dot[4 * NB * NRP]; // q . ref^T, padded
__device__ float g_r2[4 * NR];
__device__ float g_q2[4 * NB];
__device__ float g_lid[NB * 4];

// ---------------- kernel 1: spatial mean pooling (unchanged) ----------------
__global__ void __launch_bounds__(256) pool_kernel(
    const float* __restrict__ f0, const float* __restrict__ f1,
    const float* __restrict__ f2, const float* __restrict__ f3)
{
    int gw   = (blockIdx.x * 256 + threadIdx.x) >> 5;
    int lane = threadIdx.x & 31;
    if (gw >= 245760) return;

    int l, base;
    if      (gw < 16384)  { l = 0; base = 0; }
    else if (gw < 49152)  { l = 1; base = 16384; }
    else if (gw < 114688) { l = 2; base = 49152; }
    else                  { l = 3; base = 114688; }
    int row = gw - base;
    const float* f = (l == 0) ? f0 : (l == 1) ? f1 : (l == 2) ? f2 : f3;
    int HW = c_HW[l];
    const float* src = f + (size_t)row * HW;

    float s = 0.f;
    if (l < 3) {
        const float4* s4 = (const float4*)src;
        int n4 = HW >> 2;
        #pragma unroll 4
        for (int i = lane; i < n4; i += 32) {
            float4 v = s4[i];
            s += (v.x + v.y) + (v.z + v.w);
        }
    } else {
        #pragma unroll 2
        for (int i = lane; i < HW; i += 32) s += src[i];
    }
    #pragma unroll
    for (int o = 16; o > 0; o >>= 1) s += __shfl_xor_sync(0xffffffffu, s, o);
    if (lane == 0) g_fq[c_qoff[l] + row] = s / (float)HW;
}

// ---------------- kernel 2: squared norms (unchanged) ----------------
__global__ void __launch_bounds__(256) norms_kernel(
    const float* __restrict__ r0, const float* __restrict__ r1,
    const float* __restrict__ r2, const float* __restrict__ r3)
{
    int gw   = (blockIdx.x * 256 + threadIdx.x) >> 5;
    int lane = threadIdx.x & 31;
    if (gw >= 9024) return;

    const float* src;
    float* out;
    int C;
    if (gw < 8000) {
        int l = gw / NR, row = gw % NR;
        const float* rp = (l == 0) ? r0 : (l == 1) ? r1 : (l == 2) ? r2 : r3;
        C = c_C[l];
        src = rp + (size_t)row * C;
        out = g_r2 + l * NR + row;
    } else {
        int idx = gw - 8000;
        int l = idx >> 8, row = idx & 255;
        C = c_C[l];
        src = g_fq + c_qoff[l] + (size_t)row * C;
        out = g_q2 + l * NB + row;
    }
    float s = 0.f;
    const float4* s4 = (const float4*)src;
    int n4 = C >> 2;
    #pragma unroll 4
    for (int i = lane; i < n4; i += 32) {
        float4 v = s4[i];
        s += v.x * v.x + v.y * v.y + v.z * v.z + v.w * v.w;
    }
    #pragma unroll
    for (int o = 16; o > 0; o >>= 1) s += __shfl_xor_sync(0xffffffffu, s, o);
    if (lane == 0) *out = s;
}

// ---------------- kernel 3: 64x64 tile, 128 threads, 8x4 acc, K-chunk 16 ----------------
__global__ void __launch_bounds__(128) dist_gemm_kernel(
    const float* __restrict__ r0, const float* __restrict__ r1,
    const float* __restrict__ r2, const float* __restrict__ r3)
{
    int l = 3 - blockIdx.z;     // heavy layers first -> short tail
    int C = c_C[l];
    const float* ref = (l == 0) ? r0 : (l == 1) ? r1 : (l == 2) ? r2 : r3;
    const float* q   = g_fq + c_qoff[l];

    int bt = blockIdx.y << 6;
    int rt = blockIdx.x << 6;

    __shared__ __align__(16) float qs[2][16][68];
    __shared__ __align__(16) float rs[2][16][68];

    int tx = threadIdx.x;   // 0..15 -> ref cols tx*4
    int ty = threadIdx.y;   // 0..7  -> batch rows ty*8
    int tid = ty * 16 + tx;

    // loaders: tid 0..63 -> q row tid; tid 64..127 -> r row tid-64
    int isR  = tid >> 6;
    int lrow = tid & 63;
    const float* gsrc;
    size_t gbase;
    int valid;
    if (isR) {
        int rr = rt + lrow;
        valid = (rr < NR);
        gbase = (size_t)(valid ? rr : 0) * C;
        gsrc  = ref;
    } else {
        valid = 1;
        gbase = (size_t)(bt + lrow) * C;
        gsrc  = q;
    }
    float* sbuf0 = (isR ? &rs[0][0][0] : &qs[0][0][0]) + lrow;
    float* sbuf1 = (isR ? &rs[1][0][0] : &qs[1][0][0]) + lrow;

    float acc[8][4];
    #pragma unroll
    for (int i = 0; i < 8; i++)
        #pragma unroll
        for (int j = 0; j < 4; j++) acc[i][j] = 0.f;

    // prologue: chunk 0 -> buffer 0 (each loader: one row, 16 k-values)
    {
        float4 p[4];
        #pragma unroll
        for (int g = 0; g < 4; g++)
            p[g] = valid ? *(const float4*)&gsrc[gbase + g * 4]
                         : make_float4(0.f, 0.f, 0.f, 0.f);
        #pragma unroll
        for (int g = 0; g < 4; g++) {
            sbuf0[(g * 4 + 0) * 68] = p[g].x;
            sbuf0[(g * 4 + 1) * 68] = p[g].y;
            sbuf0[(g * 4 + 2) * 68] = p[g].z;
            sbuf0[(g * 4 + 3) * 68] = p[g].w;
        }
    }

    int nch = C >> 4;
    for (int ch = 0; ch < nch; ch++) {
        __syncthreads();
        int buf = ch & 1;

        float4 n[4];
        #pragma unroll
        for (int g = 0; g < 4; g++) n[g] = make_float4(0.f, 0.f, 0.f, 0.f);
        if (ch + 1 < nch && valid) {
            size_t o = gbase + (size_t)(ch + 1) * 16;
            #pragma unroll
            for (int g = 0; g < 4; g++)
                n[g] = *(const float4*)&gsrc[o + g * 4];
        }

        #pragma unroll
        for (int kk = 0; kk < 16; kk++) {
            float4 q0 = *(const float4*)&qs[buf][kk][ty * 8];
            float4 q1 = *(const float4*)&qs[buf][kk][ty * 8 + 4];
            float4 rv = *(const float4*)&rs[buf][kk][tx * 4];
            acc[0][0] += q0.x * rv.x; acc[0][1] += q0.x * rv.y;
            acc[0][2] += q0.x * rv.z; acc[0][3] += q0.x * rv.w;
            acc[1][0] += q0.y * rv.x; acc[1][1] += q0.y * rv.y;
            acc[1][2] += q0.y * rv.z; acc[1][3] += q0.y * rv.w;
            acc[2][0] += q0.z * rv.x; acc[2][1] += q0.z * rv.y;
            acc[2][2] += q0.z * rv.z; acc[2][3] += q0.z * rv.w;
            acc[3][0] += q0.w * rv.x; acc[3][1] += q0.w * rv.y;
            acc[3][2] += q0.w * rv.z; acc[3][3] += q0.w * rv.w;
            acc[4][0] += q1.x * rv.x; acc[4][1] += q1.x * rv.y;
            acc[4][2] += q1.x * rv.z; acc[4][3] += q1.x * rv.w;
            acc[5][0] += q1.y * rv.x; acc[5][1] += q1.y * rv.y;
            acc[5][2] += q1.y * rv.z; acc[5][3] += q1.y * rv.w;
            acc[6][0] += q1.z * rv.x; acc[6][1] += q1.z * rv.y;
            acc[6][2] += q1.z * rv.z; acc[6][3] += q1.z * rv.w;
            acc[7][0] += q1.w * rv.x; acc[7][1] += q1.w * rv.y;
            acc[7][2] += q1.w * rv.z; acc[7][3] += q1.w * rv.w;
        }

        if (ch + 1 < nch) {
            float* d = buf ? sbuf0 : sbuf1;
            #pragma unroll
            for (int g = 0; g < 4; g++) {
                d[(g * 4 + 0) * 68] = n[g].x;
                d[(g * 4 + 1) * 68] = n[g].y;
                d[(g * 4 + 2) * 68] = n[g].z;
                d[(g * 4 + 3) * 68] = n[g].w;
            }
        }
    }

    float* out = g_dot + ((size_t)l * NB + bt) * NRP + rt;
    #pragma unroll
    for (int i = 0; i < 8; i++) {
        *(float4*)&out[(size_t)(ty * 8 + i) * NRP + tx * 4] =
            make_float4(acc[i][0], acc[i][1], acc[i][2], acc[i][3]);
    }
}

// ---------------- kernel 4: radix rank-select + LID (no sorting, no extraction loop) ----------------
__global__ void __launch_bounds__(256) select_kernel(const int* __restrict__ kp)
{
    int b = blockIdx.x;
    int l = blockIdx.y;
    int tid  = threadIdx.x;
    int warp = tid >> 5;
    int lane = tid & 31;

    __shared__ unsigned wh[8][16];     // per-warp digit counts
    __shared__ unsigned sh_pref;
    __shared__ int      sh_rank;
    __shared__ unsigned sh_wmin[8];
    __shared__ int      sh_owner;
    __shared__ float    sh_fsum[8];
    __shared__ int      sh_cnt[8];

    const float* dotp = g_dot + ((size_t)l * NB + b) * NRP;
    const float* r2p  = g_r2 + l * NR;
    float q2v = g_q2[l * NB + b];

    // distances as uint bits (nonneg floats: bit order == value order)
    int base = tid * 8;
    float4 d0 = *(const float4*)&dotp[base];
    float4 d1 = *(const float4*)&dotp[base + 4];
    float dd[8] = {d0.x, d0.y, d0.z, d0.w, d1.x, d1.y, d1.z, d1.w};
    unsigned u[8];
    #pragma unroll
    for (int j = 0; j < 8; j++) {
        int r = base + j;
        float x = (r < NR) ? fmaxf(q2v + r2p[r] - 2.f * dd[j], 0.f) : FLT_MAX;
        u[j] = __float_as_uint(x);
    }

    int kk  = *kp;
    int kp1 = kk + 1;

    if (tid == 0) { sh_owner = 0x7fffffff; }

    // block min (the dropped nearest neighbor)
    unsigned lm = min(min(min(u[0], u[1]), min(u[2], u[3])),
                      min(min(u[4], u[5]), min(u[6], u[7])));
    unsigned wm = __reduce_min_sync(0xffffffffu, lm);
    if (lane == 0) sh_wmin[warp] = wm;
    __syncthreads();
    unsigned bm = sh_wmin[0];
    #pragma unroll
    for (int w = 1; w < 8; w++) bm = min(bm, sh_wmin[w]);

    // 8-pass 4-bit MSB radix: find T = kp1-th smallest value exactly
    unsigned prefix = 0;
    int rank = kp1;
    #pragma unroll
    for (int pass = 0; pass < 8; pass++) {
        int shift = 28 - pass * 4;
        unsigned lo = 0, hi = 0;   // 8 nibble counters each (per-thread count <= 8)
        #pragma unroll
        for (int j = 0; j < 8; j++) {
            bool active = (pass == 0) ? true
                          : (((u[j] ^ prefix) >> (shift + 4)) == 0u);
            unsigned dig = (u[j] >> shift) & 15u;
            unsigned inc = active ? (1u << ((dig & 7u) * 4u)) : 0u;
            if (dig & 8u) hi += inc; else lo += inc;
        }
        #pragma unroll
        for (int d = 0; d < 16; d++) {
            unsigned c = (d < 8) ? ((lo >> (d * 4)) & 15u)
                                 : ((hi >> ((d - 8) * 4)) & 15u);
            unsigned t = __reduce_add_sync(0xffffffffu, c);
            if (lane == d) wh[warp][d] = t;
        }
        __syncthreads();
        if (warp == 0 && lane < 16) {
            unsigned tot = 0;
            #pragma unroll
            for (int w = 0; w < 8; w++) tot += wh[w][lane];
            unsigned cum = tot;
            #pragma unroll
            for (int o = 1; o < 16; o <<= 1) {
                unsigned v = __shfl_up_sync(0x0000ffffu, cum, o);
                if (lane >= o) cum += v;
            }
            unsigned ball = __ballot_sync(0x0000ffffu, (int)cum >= rank);
            int D = __ffs(ball) - 1;
            if (lane == D) {
                sh_pref = prefix | ((unsigned)D << shift);
                sh_rank = rank - (int)(cum - tot);
            }
        }
        __syncthreads();
        prefix = sh_pref;
        rank   = sh_rank;
    }
    unsigned T = prefix;   // exact kp1-th smallest squared distance (bits)

    // elect single owner of the min (drop exactly one instance)
    bool has = false;
    #pragma unroll
    for (int j = 0; j < 8; j++) has |= (u[j] == bm);
    if (has) atomicMin(&sh_owner, tid);
    __syncthreads();
    int skip = -1;
    if (tid == sh_owner) {
        #pragma unroll
        for (int j = 0; j < 8; j++)
            if (skip < 0 && u[j] == bm) skip = j;
    }

    // sum of ln over the kp1 smallest, excluding the min; count strict-below-T
    float sl = 0.f;
    int cl = 0;
    #pragma unroll
    for (int j = 0; j < 8; j++) {
        if (u[j] < T) {
            cl++;
            if (j != skip) sl += logf(__uint_as_float(u[j]));
        }
    }
    #pragma unroll
    for (int o = 16; o > 0; o >>= 1) sl += __shfl_xor_sync(0xffffffffu, sl, o);
    cl = (int)__reduce_add_sync(0xffffffffu, (unsigned)cl);
    if (lane == 0) { sh_fsum[warp] = sl; sh_cnt[warp] = cl; }
    __syncthreads();
    if (tid == 0) {
        float S = 0.f; int Ct = 0;
        #pragma unroll
        for (int w = 0; w < 8; w++) { S += sh_fsum[w]; Ct += sh_cnt[w]; }
        int m = kp1 - Ct;            // copies of T included in the set (>=1)
        float lnT = logf(__uint_as_float(T));
        // s = sum over k neighbors of log(d_i / d_k) = 0.5*(S + m*lnT - kk*lnT)
        float s = 0.5f * (S + (float)(m - kk) * lnT);
        g_lid[b * 4 + l] = -(float)kk / s;
    }
}

// ---------------- kernel 5: linear head + sigmoid ----------------
__global__ void final_kernel(const float* __restrict__ w,
                             const float* __restrict__ bb,
                             float* __restrict__ out)
{
    int b = threadIdx.x;
    float z = bb[0];
    #pragma unroll
    for (int j = 0; j < 4; j++) z += g_lid[b * 4 + j] * w[j];
    out[b] = 1.f / (1.f + expf(-z));
}

// ---------------- launch ----------------
extern "C" void kernel_launch(void* const* d_in, const int* in_sizes, int n_in,
                              void* d_out, int out_size)
{
    const float* feat[4] = {0, 0, 0, 0};
    const float* ref[4]  = {0, 0, 0, 0};
    const float* rw = 0;
    const float* rb = 0;
    const int*   kp = 0;
    int ones = 0;
    for (int i = 0; i < n_in; i++) {
        switch (in_sizes[i]) {
            case 51380224: feat[0] = (const float*)d_in[i]; break;
            case 25690112: feat[1] = (const float*)d_in[i]; break;
            case 12845056: feat[2] = (const float*)d_in[i]; break;
            case 6422528:  feat[3] = (const float*)d_in[i]; break;
            case 128000:   ref[0]  = (const float*)d_in[i]; break;
            case 256000:   ref[1]  = (const float*)d_in[i]; break;
            case 512000:   ref[2]  = (const float*)d_in[i]; break;
            case 1024000:  ref[3]  = (const float*)d_in[i]; break;
            case 4:        rw      = (const float*)d_in[i]; break;
            case 1:
                if (ones++ == 0) rb = (const float*)d_in[i];
                else             kp = (const int*)d_in[i];
                break;
            default: break;
        }
    }

    pool_kernel<<<30720, 256>>>(feat[0], feat[1], feat[2], feat[3]);
    norms_kernel<<<1128, 256>>>(ref[0], ref[1], ref[2], ref[3]);

    dim3 gg(NRP / 64, NB / 64, 4);   // (32, 4, 4) = 512 blocks; z reversed inside
    dim3 bt(16, 8);                  // 128 threads
    dist_gemm_kernel<<<gg, bt>>>(ref[0], ref[1], ref[2], ref[3]);

    dim3 gs(NB, 4);
    select_kernel<<<gs, 256>>>(kp);

    final_kernel<<<1, 256>>>(rw, rb, (float*)d_out);
}

// round 10
// speedup vs baseline: 1.0587x; 1.0587x over previous
#include <cuda_runtime.h>
#include <math.h>
#include <float.h>

// layers: C = {64,128,256,512}, HW = {3136,784,196,49}, B=256, R=2000
#define NB 256
#define NR 2000
#define NRP 2048

__constant__ int c_C[4]    = {64, 128, 256, 512};
__constant__ int c_HW[4]   = {3136, 784, 196, 49};
__constant__ int c_qoff[4] = {0, 16384, 49152, 114688};

// scratch (static device globals; no allocation)
__device__ __align__(16) float g_fq[245760];        // pooled queries
__device__ __align__(16) float g_dot[4 * NB * NRP]; // q . ref^T, padded
__device__ float g_r2[4 * NR];
__device__ float g_q2[4 * NB];
__device__ float g_lid[NB * 4];

// ---------------- kernel 1: spatial mean pooling (unchanged) ----------------
__global__ void __launch_bounds__(256) pool_kernel(
    const float* __restrict__ f0, const float* __restrict__ f1,
    const float* __restrict__ f2, const float* __restrict__ f3)
{
    int gw   = (blockIdx.x * 256 + threadIdx.x) >> 5;
    int lane = threadIdx.x & 31;
    if (gw >= 245760) return;

    int l, base;
    if      (gw < 16384)  { l = 0; base = 0; }
    else if (gw < 49152)  { l = 1; base = 16384; }
    else if (gw < 114688) { l = 2; base = 49152; }
    else                  { l = 3; base = 114688; }
    int row = gw - base;
    const float* f = (l == 0) ? f0 : (l == 1) ? f1 : (l == 2) ? f2 : f3;
    int HW = c_HW[l];
    const float* src = f + (size_t)row * HW;

    float s = 0.f;
    if (l < 3) {
        const float4* s4 = (const float4*)src;
        int n4 = HW >> 2;
        #pragma unroll 4
        for (int i = lane; i < n4; i += 32) {
            float4 v = s4[i];
            s += (v.x + v.y) + (v.z + v.w);
        }
    } else {
        #pragma unroll 2
        for (int i = lane; i < HW; i += 32) s += src[i];
    }
    #pragma unroll
    for (int o = 16; o > 0; o >>= 1) s += __shfl_xor_sync(0xffffffffu, s, o);
    if (lane == 0) g_fq[c_qoff[l] + row] = s / (float)HW;
}

// ---------------- kernel 2: squared norms (unchanged) ----------------
__global__ void __launch_bounds__(256) norms_kernel(
    const float* __restrict__ r0, const float* __restrict__ r1,
    const float* __restrict__ r2, const float* __restrict__ r3)
{
    int gw   = (blockIdx.x * 256 + threadIdx.x) >> 5;
    int lane = threadIdx.x & 31;
    if (gw >= 9024) return;

    const float* src;
    float* out;
    int C;
    if (gw < 8000) {
        int l = gw / NR, row = gw % NR;
        const float* rp = (l == 0) ? r0 : (l == 1) ? r1 : (l == 2) ? r2 : r3;
        C = c_C[l];
        src = rp + (size_t)row * C;
        out = g_r2 + l * NR + row;
    } else {
        int idx = gw - 8000;
        int l = idx >> 8, row = idx & 255;
        C = c_C[l];
        src = g_fq + c_qoff[l] + (size_t)row * C;
        out = g_q2 + l * NB + row;
    }
    float s = 0.f;
    const float4* s4 = (const float4*)src;
    int n4 = C >> 2;
    #pragma unroll 4
    for (int i = lane; i < n4; i += 32) {
        float4 v = s4[i];
        s += v.x * v.x + v.y * v.y + v.z * v.z + v.w * v.w;
    }
    #pragma unroll
    for (int o = 16; o > 0; o >>= 1) s += __shfl_xor_sync(0xffffffffu, s, o);
    if (lane == 0) *out = s;
}

// ---------------- kernel 3: 128x64 tile, 256 threads, 8x4 acc, K-chunk 16 ----------------
__global__ void __launch_bounds__(256) dist_gemm_kernel(
    const float* __restrict__ r0, const float* __restrict__ r1,
    const float* __restrict__ r2, const float* __restrict__ r3)
{
    int l = 3 - blockIdx.z;     // heavy layers first -> short tail
    int C = c_C[l];
    const float* ref = (l == 0) ? r0 : (l == 1) ? r1 : (l == 2) ? r2 : r3;
    const float* q   = g_fq + c_qoff[l];

    int bt = blockIdx.y << 7;   // batch tile (128)
    int rt = blockIdx.x << 6;   // ref tile (64)

    __shared__ __align__(16) float qs[2][16][132];  // [k][batch row]
    __shared__ __align__(16) float rs[2][16][68];   // [k][ref row]

    int tx = threadIdx.x;   // 0..15 -> ref cols tx*4
    int ty = threadIdx.y;   // 0..15 -> batch rows ty*8..+7
    int tid = ty * 16 + tx;

    // loaders: tid 0..127 -> q row tid (16 k-floats);
    //          tid 128..255 -> r row (tid-128)>>1, k-half (tid-128)&1 (8 k-floats)
    int isR  = tid >> 7;
    int qrow = tid & 127;
    int rrow = (tid & 127) >> 1;
    int rkg  = tid & 1;

    const float* gsrc;
    size_t gbase;
    int valid;
    if (isR) {
        int rr = rt + rrow;
        valid = (rr < NR);
        gbase = (size_t)(valid ? rr : 0) * C;
        gsrc  = ref;
    } else {
        valid = 1;
        gbase = (size_t)(bt + qrow) * C;
        gsrc  = q;
    }
    float* sq0 = &qs[0][0][0] + qrow;
    float* sq1 = &qs[1][0][0] + qrow;
    float* sr0 = &rs[0][0][0] + rrow;
    float* sr1 = &rs[1][0][0] + rrow;

    float acc[8][4];
    #pragma unroll
    for (int i = 0; i < 8; i++)
        #pragma unroll
        for (int j = 0; j < 4; j++) acc[i][j] = 0.f;

    // prologue: chunk 0 -> buffer 0
    if (!isR) {
        #pragma unroll
        for (int g = 0; g < 4; g++) {
            float4 v = *(const float4*)&gsrc[gbase + g * 4];
            sq0[(g * 4 + 0) * 132] = v.x;
            sq0[(g * 4 + 1) * 132] = v.y;
            sq0[(g * 4 + 2) * 132] = v.z;
            sq0[(g * 4 + 3) * 132] = v.w;
        }
    } else {
        #pragma unroll
        for (int g = 0; g < 2; g++) {
            float4 v = valid ? *(const float4*)&gsrc[gbase + rkg * 8 + g * 4]
                             : make_float4(0.f, 0.f, 0.f, 0.f);
            sr0[(rkg * 8 + g * 4 + 0) * 68] = v.x;
            sr0[(rkg * 8 + g * 4 + 1) * 68] = v.y;
            sr0[(rkg * 8 + g * 4 + 2) * 68] = v.z;
            sr0[(rkg * 8 + g * 4 + 3) * 68] = v.w;
        }
    }

    int nch = C >> 4;
    for (int ch = 0; ch < nch; ch++) {
        __syncthreads();
        int buf = ch & 1;

        // prefetch next chunk into regs
        float4 n0 = make_float4(0.f, 0.f, 0.f, 0.f);
        float4 n1 = make_float4(0.f, 0.f, 0.f, 0.f);
        float4 n2 = make_float4(0.f, 0.f, 0.f, 0.f);
        float4 n3 = make_float4(0.f, 0.f, 0.f, 0.f);
        if (ch + 1 < nch && valid) {
            size_t o = gbase + (size_t)(ch + 1) * 16;
            if (!isR) {
                n0 = *(const float4*)&gsrc[o];
                n1 = *(const float4*)&gsrc[o + 4];
                n2 = *(const float4*)&gsrc[o + 8];
                n3 = *(const float4*)&gsrc[o + 12];
            } else {
                n0 = *(const float4*)&gsrc[o + rkg * 8];
                n1 = *(const float4*)&gsrc[o + rkg * 8 + 4];
            }
        }

        // compute chunk ch: 16 k-steps x 32 FFMA
        #pragma unroll
        for (int kk = 0; kk < 16; kk++) {
            float4 q0 = *(const float4*)&qs[buf][kk][ty * 8];
            float4 q1 = *(const float4*)&qs[buf][kk][ty * 8 + 4];
            float4 rv = *(const float4*)&rs[buf][kk][tx * 4];
            acc[0][0] += q0.x * rv.x; acc[0][1] += q0.x * rv.y;
            acc[0][2] += q0.x * rv.z; acc[0][3] += q0.x * rv.w;
            acc[1][0] += q0.y * rv.x; acc[1][1] += q0.y * rv.y;
            acc[1][2] += q0.y * rv.z; acc[1][3] += q0.y * rv.w;
            acc[2][0] += q0.z * rv.x; acc[2][1] += q0.z * rv.y;
            acc[2][2] += q0.z * rv.z; acc[2][3] += q0.z * rv.w;
            acc[3][0] += q0.w * rv.x; acc[3][1] += q0.w * rv.y;
            acc[3][2] += q0.w * rv.z; acc[3][3] += q0.w * rv.w;
            acc[4][0] += q1.x * rv.x; acc[4][1] += q1.x * rv.y;
            acc[4][2] += q1.x * rv.z; acc[4][3] += q1.x * rv.w;
            acc[5][0] += q1.y * rv.x; acc[5][1] += q1.y * rv.y;
            acc[5][2] += q1.y * rv.z; acc[5][3] += q1.y * rv.w;
            acc[6][0] += q1.z * rv.x; acc[6][1] += q1.z * rv.y;
            acc[6][2] += q1.z * rv.z; acc[6][3] += q1.z * rv.w;
            acc[7][0] += q1.w * rv.x; acc[7][1] += q1.w * rv.y;
            acc[7][2] += q1.w * rv.z; acc[7][3] += q1.w * rv.w;
        }

        // store prefetched chunk into the other buffer (consumed pre-barrier)
        if (ch + 1 < nch) {
            if (!isR) {
                float* d = buf ? sq0 : sq1;
                d[0 * 132]  = n0.x; d[1 * 132]  = n0.y; d[2 * 132]  = n0.z; d[3 * 132]  = n0.w;
                d[4 * 132]  = n1.x; d[5 * 132]  = n1.y; d[6 * 132]  = n1.z; d[7 * 132]  = n1.w;
                d[8 * 132]  = n2.x; d[9 * 132]  = n2.y; d[10 * 132] = n2.z; d[11 * 132] = n2.w;
                d[12 * 132] = n3.x; d[13 * 132] = n3.y; d[14 * 132] = n3.z; d[15 * 132] = n3.w;
            } else {
                float* d = buf ? sr0 : sr1;
                d[(rkg * 8 + 0) * 68] = n0.x; d[(rkg * 8 + 1) * 68] = n0.y;
                d[(rkg * 8 + 2) * 68] = n0.z; d[(rkg * 8 + 3) * 68] = n0.w;
                d[(rkg * 8 + 4) * 68] = n1.x; d[(rkg * 8 + 5) * 68] = n1.y;
                d[(rkg * 8 + 6) * 68] = n1.z; d[(rkg * 8 + 7) * 68] = n1.w;
            }
        }
    }

    float* out = g_dot + ((size_t)l * NB + bt) * NRP + rt;
    #pragma unroll
    for (int i = 0; i < 8; i++) {
        *(float4*)&out[(size_t)(ty * 8 + i) * NRP + tx * 4] =
            make_float4(acc[i][0], acc[i][1], acc[i][2], acc[i][3]);
    }
}

// ---------------- kernel 4: extraction with uint mins + REDUX (proven R8 version) ----------------
__global__ void __launch_bounds__(256) select_kernel(const int* __restrict__ kp)
{
    int b = blockIdx.x;
    int l = blockIdx.y;
    int tid  = threadIdx.x;
    int warp = tid >> 5;
    int lane = tid & 31;

    __shared__ unsigned wv[2][8];
    __shared__ float topd[64];

    const float* dotp = g_dot + ((size_t)l * NB + b) * NRP;
    const float* r2p  = g_r2 + l * NR;
    float q2v = g_q2[l * NB + b];

    int base = tid * 8;
    float4 d0 = *(const float4*)&dotp[base];
    float4 d1 = *(const float4*)&dotp[base + 4];
    float dd[8] = {d0.x, d0.y, d0.z, d0.w, d1.x, d1.y, d1.z, d1.w};
    unsigned u[8];
    #pragma unroll
    for (int j = 0; j < 8; j++) {
        int r = base + j;
        float x = (r < NR) ? fmaxf(q2v + r2p[r] - 2.f * dd[j], 0.f) : FLT_MAX;
        u[j] = __float_as_uint(x);
    }

    int kk  = *kp;
    int kp1 = min(kk + 1, 64);

    for (int t = 0; t < kp1; t++) {
        unsigned a0 = min(u[0], u[1]), a1 = min(u[2], u[3]);
        unsigned a2 = min(u[4], u[5]), a3 = min(u[6], u[7]);
        unsigned lm = min(min(a0, a1), min(a2, a3));
        unsigned wm = __reduce_min_sync(0xffffffffu, lm);
        unsigned bal = __ballot_sync(0xffffffffu, lm == wm);
        bool leader = (lane == (__ffs(bal) - 1));
        int p = t & 1;
        if (lane == 0) wv[p][warp] = wm;
        __syncthreads();
        unsigned bm = wv[p][0]; int bw = 0;
        #pragma unroll
        for (int w = 1; w < 8; w++) {
            unsigned x = wv[p][w];
            if (x < bm) { bm = x; bw = w; }
        }
        if (tid == 0) topd[t] = __uint_as_float(bm);
        if (warp == bw && leader) {
            bool done = false;
            #pragma unroll
            for (int j = 0; j < 8; j++)
                if (!done && u[j] == wm) { u[j] = 0xFFFFFFFFu; done = true; }
        }
    }
    __syncthreads();

    if (warp == 0) {
        float dk = sqrtf(topd[kp1 - 1]);
        float s = 0.f;
        for (int i = lane; i < kp1; i += 32)
            if (i >= 1) s += logf(sqrtf(topd[i]) / dk);
        #pragma unroll
        for (int o = 16; o > 0; o >>= 1) s += __shfl_xor_sync(0xffffffffu, s, o);
        if (lane == 0) g_lid[b * 4 + l] = -(float)kk / s;
    }
}

// ---------------- kernel 5: linear head + sigmoid ----------------
__global__ void final_kernel(const float* __restrict__ w,
                             const float* __restrict__ bb,
                             float* __restrict__ out)
{
    int b = threadIdx.x;
    float z = bb[0];
    #pragma unroll
    for (int j = 0; j < 4; j++) z += g_lid[b * 4 + j] * w[j];
    out[b] = 1.f / (1.f + expf(-z));
}

// ---------------- launch ----------------
extern "C" void kernel_launch(void* const* d_in, const int* in_sizes, int n_in,
                              void* d_out, int out_size)
{
    const float* feat[4] = {0, 0, 0, 0};
    const float* ref[4]  = {0, 0, 0, 0};
    const float* rw = 0;
    const float* rb = 0;
    const int*   kp = 0;
    int ones = 0;
    for (int i = 0; i < n_in; i++) {
        switch (in_sizes[i]) {
            case 51380224: feat[0] = (const float*)d_in[i]; break;
            case 25690112: feat[1] = (const float*)d_in[i]; break;
            case 12845056: feat[2] = (const float*)d_in[i]; break;
            case 6422528:  feat[3] = (const float*)d_in[i]; break;
            case 128000:   ref[0]  = (const float*)d_in[i]; break;
            case 256000:   ref[1]  = (const float*)d_in[i]; break;
            case 512000:   ref[2]  = (const float*)d_in[i]; break;
            case 1024000:  ref[3]  = (const float*)d_in[i]; break;
            case 4:        rw      = (const float*)d_in[i]; break;
            case 1:
                if (ones++ == 0) rb = (const float*)d_in[i];
                else             kp = (const int*)d_in[i];
                break;
            default: break;
        }
    }

    pool_kernel<<<30720, 256>>>(feat[0], feat[1], feat[2], feat[3]);
    norms_kernel<<<1128, 256>>>(ref[0], ref[1], ref[2], ref[3]);

    dim3 gg(NRP / 64, NB / 128, 4);  // (32, 2, 4) = 256 blocks; z reversed inside
    dim3 bt(16, 16);                 // 256 threads, 8 warps
    dist_gemm_kernel<<<gg, bt>>>(ref[0], ref[1], ref[2], ref[3]);

    dim3 gs(NB, 4);
    select_kernel<<<gs, 256>>>(kp);

    final_kernel<<<1, 256>>>(rw, rb, (float*)d_out);
}